// round 2
// baseline (speedup 1.0000x reference)
#include <cuda_runtime.h>
#include <cuda_bf16.h>

// Problem constants
#define BATCH   16384
#define IN_DIM  784
#define INTER   1024
#define CODE    2048   // STRIPE_DIM(64) * NUM_STRIPES(32)
#define KNEUR   64
#define KSTRIPE 4
#define NSTRIPE 32

// Scratch (device globals; no allocation allowed)
__device__ float g_h[(size_t)BATCH * INTER];     // 64 MB
__device__ float g_c[(size_t)BATCH * CODE];      // 128 MB
__device__ float g_d[(size_t)BATCH * INTER];     // 64 MB
__device__ float g_W3t[(size_t)CODE * INTER];    // 8 MB
__device__ float g_vals[(size_t)BATCH * KNEUR];
__device__ int   g_idx[(size_t)BATCH * KNEUR];
__device__ int   g_cnt[BATCH];

// ---------------------------------------------------------------------------
// fp64-accumulate GEMM: C[M,N] = relu(A[M,K] @ B[N,K]^T + bias[N]), fp32 I/O.
// Used for GEMM1/GEMM2 so that c is correctly rounded — the top-k selection
// decisions are chaotic amplifiers, so my c must be as close to the true
// value as possible.
// BM=BN=64, BK=16, 256 threads, 4x4 fp64 microtile.
// ---------------------------------------------------------------------------
#define DBM 64
#define DBN 64
#define DBK 16
#define DPAD 2

__global__ __launch_bounds__(256)
void dgemm_bias_relu(const float* __restrict__ A, const float* __restrict__ B,
                     const float* __restrict__ bias, float* __restrict__ C,
                     int M, int N, int K)
{
    __shared__ double As[DBK][DBM + DPAD];
    __shared__ double Bs[DBK][DBN + DPAD];

    const int tid  = threadIdx.x;
    const int row0 = blockIdx.y * DBM;
    const int col0 = blockIdx.x * DBN;
    const int tx = tid % 16;       // col group
    const int ty = tid / 16;       // row group

    double acc[4][4];
    #pragma unroll
    for (int i = 0; i < 4; ++i)
        #pragma unroll
        for (int j = 0; j < 4; ++j) acc[i][j] = 0.0;

    const int r  = tid >> 2;        // 0..63
    const int kq = (tid & 3) * 4;   // 0,4,8,12

    for (int k0 = 0; k0 < K; k0 += DBK) {
        // A tile: 64 rows x 16 k = 256 float4 loads, one per thread
        {
            float4 v = *reinterpret_cast<const float4*>(A + (size_t)(row0 + r) * K + k0 + kq);
            As[kq + 0][r] = (double)v.x; As[kq + 1][r] = (double)v.y;
            As[kq + 2][r] = (double)v.z; As[kq + 3][r] = (double)v.w;
        }
        // B tile (N guarded)
        {
            float4 v = make_float4(0.f, 0.f, 0.f, 0.f);
            if (col0 + r < N)
                v = *reinterpret_cast<const float4*>(B + (size_t)(col0 + r) * K + k0 + kq);
            Bs[kq + 0][r] = (double)v.x; Bs[kq + 1][r] = (double)v.y;
            Bs[kq + 2][r] = (double)v.z; Bs[kq + 3][r] = (double)v.w;
        }
        __syncthreads();

        #pragma unroll
        for (int kk = 0; kk < DBK; ++kk) {
            double ra[4], rb[4];
            #pragma unroll
            for (int i = 0; i < 4; ++i) ra[i] = As[kk][ty * 4 + i];
            #pragma unroll
            for (int j = 0; j < 4; ++j) rb[j] = Bs[kk][tx * 4 + j];
            #pragma unroll
            for (int i = 0; i < 4; ++i)
                #pragma unroll
                for (int j = 0; j < 4; ++j)
                    acc[i][j] = fma(ra[i], rb[j], acc[i][j]);
        }
        __syncthreads();
    }

    #pragma unroll
    for (int i = 0; i < 4; ++i) {
        int rr = row0 + ty * 4 + i;
        #pragma unroll
        for (int j = 0; j < 4; ++j) {
            int cc = col0 + tx * 4 + j;
            if (cc < N) {
                float v = (float)(acc[i][j] + (double)bias[cc]);
                C[(size_t)rr * N + cc] = fmaxf(v, 0.f);
            }
        }
    }
}

// ---------------------------------------------------------------------------
// fp32 tiled GEMM (for GEMM4 — final layer, no selection chaos downstream)
// ---------------------------------------------------------------------------
#define BM 128
#define BN 128
#define BKK 16
#define TM 8
#define TN 8
#define PAD 4

__global__ __launch_bounds__(256)
void sgemm_bias_relu(const float* __restrict__ A, const float* __restrict__ B,
                     const float* __restrict__ bias, float* __restrict__ C,
                     int M, int N, int K)
{
    __shared__ float As[BKK][BM + PAD];
    __shared__ float Bs[BKK][BN + PAD];

    const int tid  = threadIdx.x;
    const int row0 = blockIdx.y * BM;
    const int col0 = blockIdx.x * BN;
    const int tx = tid % 16;
    const int ty = tid / 16;

    float acc[TM][TN];
    #pragma unroll
    for (int i = 0; i < TM; ++i)
        #pragma unroll
        for (int j = 0; j < TN; ++j) acc[i][j] = 0.f;

    for (int k0 = 0; k0 < K; k0 += BKK) {
        #pragma unroll
        for (int it = 0; it < 2; ++it) {
            int fi = tid + it * 256;
            int r  = fi >> 2;
            int kq = (fi & 3) * 4;
            float4 v = *reinterpret_cast<const float4*>(A + (size_t)(row0 + r) * K + k0 + kq);
            As[kq + 0][r] = v.x; As[kq + 1][r] = v.y;
            As[kq + 2][r] = v.z; As[kq + 3][r] = v.w;
        }
        #pragma unroll
        for (int it = 0; it < 2; ++it) {
            int fi = tid + it * 256;
            int r  = fi >> 2;
            int kq = (fi & 3) * 4;
            float4 v = make_float4(0.f, 0.f, 0.f, 0.f);
            if (col0 + r < N)
                v = *reinterpret_cast<const float4*>(B + (size_t)(col0 + r) * K + k0 + kq);
            Bs[kq + 0][r] = v.x; Bs[kq + 1][r] = v.y;
            Bs[kq + 2][r] = v.z; Bs[kq + 3][r] = v.w;
        }
        __syncthreads();

        #pragma unroll
        for (int kk = 0; kk < BKK; ++kk) {
            float ra[TM], rb[TN];
            #pragma unroll
            for (int i = 0; i < TM; ++i) ra[i] = As[kk][ty * TM + i];
            #pragma unroll
            for (int j = 0; j < TN; ++j) rb[j] = Bs[kk][tx * TN + j];
            #pragma unroll
            for (int i = 0; i < TM; ++i)
                #pragma unroll
                for (int j = 0; j < TN; ++j)
                    acc[i][j] = fmaf(ra[i], rb[j], acc[i][j]);
        }
        __syncthreads();
    }

    #pragma unroll
    for (int i = 0; i < TM; ++i) {
        int r = row0 + ty * TM + i;
        #pragma unroll
        for (int j = 0; j < TN; ++j) {
            int c = col0 + tx * TN + j;
            if (c < N)
                C[(size_t)r * N + c] = fmaxf(acc[i][j] + bias[c], 0.f);
        }
    }
}

// ---------------------------------------------------------------------------
// W3 [1024,2048] -> g_W3t [2048,1024]
// ---------------------------------------------------------------------------
__global__ void transpose_w3(const float* __restrict__ W3)
{
    __shared__ float t[32][33];
    int x = blockIdx.x * 32 + threadIdx.x;
    int y = blockIdx.y * 32 + threadIdx.y;
    t[threadIdx.y][threadIdx.x] = W3[(size_t)y * CODE + x];
    __syncthreads();
    int xo = blockIdx.y * 32 + threadIdx.x;
    int yo = blockIdx.x * 32 + threadIdx.y;
    g_W3t[(size_t)yo * INTER + xo] = t[threadIdx.x][threadIdx.y];
}

// ---------------------------------------------------------------------------
// Per-row top-64 of 2048 (radix select on fp32 bits; all values >= 0),
// stripe sums in fp64, top-4-of-32 stripes, compact (idx, val) emission.
// ---------------------------------------------------------------------------
__global__ __launch_bounds__(256)
void topk_compact()
{
    const int row = blockIdx.x;
    const int tid = threadIdx.x;

    __shared__ unsigned bits[CODE];
    __shared__ unsigned hist[256];
    __shared__ unsigned s_prefix;
    __shared__ int s_k;
    __shared__ double s_sum[NSTRIPE];
    __shared__ int s_mask[NSTRIPE];
    __shared__ int s_cnt;

    const unsigned* crow = reinterpret_cast<const unsigned*>(g_c + (size_t)row * CODE);
    #pragma unroll
    for (int i = 0; i < 2; ++i) {
        int f = tid + i * 256;
        reinterpret_cast<uint4*>(bits)[f] = reinterpret_cast<const uint4*>(crow)[f];
    }
    if (tid == 0) { s_prefix = 0u; s_k = KNEUR; s_cnt = 0; }
    __syncthreads();

    for (int p = 3; p >= 0; --p) {
        hist[tid] = 0u;
        __syncthreads();
        unsigned prefix = s_prefix;
        unsigned himask = (p == 3) ? 0u : (0xFFFFFFFFu << ((p + 1) * 8));
        #pragma unroll
        for (int i = 0; i < 8; ++i) {
            unsigned b = bits[tid * 8 + i];
            if ((b & himask) == prefix)
                atomicAdd(&hist[(b >> (p * 8)) & 0xFFu], 1u);
        }
        __syncthreads();
        if (tid == 0) {
            int k = s_k;
            unsigned acc = 0;
            int sel = 0;
            for (int bin = 255; bin >= 0; --bin) {
                unsigned h = hist[bin];
                if (acc + h >= (unsigned)k) { sel = bin; break; }
                acc += h;
            }
            s_prefix = prefix | ((unsigned)sel << (p * 8));
            s_k = k - (int)acc;
        }
        __syncthreads();
    }
    const unsigned T = s_prefix;

    // Neuron-masked values + fp64 stripe partial sums
    float mv[8];
    double partial = 0.0;
    #pragma unroll
    for (int i = 0; i < 8; ++i) {
        unsigned b = bits[tid * 8 + i];
        float v = __uint_as_float(b);
        float m = (b >= T) ? v : 0.f;
        mv[i] = m;
        partial += (double)m;
    }
    partial += __shfl_down_sync(0xffffffffu, partial, 4);
    partial += __shfl_down_sync(0xffffffffu, partial, 2);
    partial += __shfl_down_sync(0xffffffffu, partial, 1);
    if ((tid & 7) == 0) s_sum[tid >> 3] = partial;
    __syncthreads();

    if (tid < NSTRIPE) {
        double my = s_sum[tid];
        int c = 0;
        #pragma unroll
        for (int j = 0; j < NSTRIPE; ++j) c += (s_sum[j] > my);
        s_mask[tid] = (c < KSTRIPE);
    }
    __syncthreads();

    const int keep = s_mask[tid >> 3];
    #pragma unroll
    for (int i = 0; i < 8; ++i) {
        float m = mv[i];
        if (keep && m > 0.f) {
            int pos = atomicAdd(&s_cnt, 1);
            if (pos < KNEUR) {
                g_vals[(size_t)row * KNEUR + pos] = m;
                g_idx[(size_t)row * KNEUR + pos]  = tid * 8 + i;
            }
        }
    }
    __syncthreads();
    if (tid == 0) g_cnt[row] = min(s_cnt, KNEUR);
}

// ---------------------------------------------------------------------------
// Sparse decode: d[row,:] = relu(b3 + sum_i val_i * W3t[idx_i, :])
// ---------------------------------------------------------------------------
__global__ __launch_bounds__(256)
void sparse_decode(const float* __restrict__ b3)
{
    const int row = blockIdx.x;
    const int tid = threadIdx.x;
    __shared__ float sv[KNEUR];
    __shared__ int   si[KNEUR];

    const int cnt = g_cnt[row];
    if (tid < cnt) {
        sv[tid] = g_vals[(size_t)row * KNEUR + tid];
        si[tid] = g_idx[(size_t)row * KNEUR + tid];
    }
    __syncthreads();

    float4 acc = make_float4(0.f, 0.f, 0.f, 0.f);
    for (int i = 0; i < cnt; ++i) {
        float v = sv[i];
        float4 w = *reinterpret_cast<const float4*>(&g_W3t[(size_t)si[i] * INTER + tid * 4]);
        acc.x = fmaf(v, w.x, acc.x);
        acc.y = fmaf(v, w.y, acc.y);
        acc.z = fmaf(v, w.z, acc.z);
        acc.w = fmaf(v, w.w, acc.w);
    }
    float4 bb = *reinterpret_cast<const float4*>(b3 + tid * 4);
    float4 o;
    o.x = fmaxf(acc.x + bb.x, 0.f);
    o.y = fmaxf(acc.y + bb.y, 0.f);
    o.z = fmaxf(acc.z + bb.z, 0.f);
    o.w = fmaxf(acc.w + bb.w, 0.f);
    *reinterpret_cast<float4*>(&g_d[(size_t)row * INTER + tid * 4]) = o;
}

// ---------------------------------------------------------------------------
// Launch
// ---------------------------------------------------------------------------
extern "C" void kernel_launch(void* const* d_in, const int* in_sizes, int n_in,
                              void* d_out, int out_size)
{
    const float* x  = (const float*)d_in[0];
    const float* W1 = (const float*)d_in[1];
    const float* b1 = (const float*)d_in[2];
    const float* W2 = (const float*)d_in[3];
    const float* b2 = (const float*)d_in[4];
    const float* W3 = (const float*)d_in[5];
    const float* b3 = (const float*)d_in[6];
    const float* W4 = (const float*)d_in[7];
    const float* b4 = (const float*)d_in[8];
    float* out = (float*)d_out;

    float* h = nullptr; cudaGetSymbolAddress((void**)&h, g_h);
    float* c = nullptr; cudaGetSymbolAddress((void**)&c, g_c);
    float* d = nullptr; cudaGetSymbolAddress((void**)&d, g_d);

    dim3 blk(256);

    transpose_w3<<<dim3(CODE / 32, INTER / 32), dim3(32, 32)>>>(W3);

    // GEMM1 (fp64 accum): h = relu(x @ W1^T + b1)
    dgemm_bias_relu<<<dim3(INTER / DBN, BATCH / DBM), blk>>>(x, W1, b1, h, BATCH, INTER, IN_DIM);

    // GEMM2 (fp64 accum): c = relu(h @ W2^T + b2)
    dgemm_bias_relu<<<dim3(CODE / DBN, BATCH / DBM), blk>>>(h, W2, b2, c, BATCH, CODE, INTER);

    // Top-k masks + compaction
    topk_compact<<<BATCH, blk>>>();

    // Sparse GEMM3: d = relu(c_sparse @ W3^T + b3)
    sparse_decode<<<BATCH, blk>>>(b3);

    // GEMM4 (fp32): out = relu(d @ W4^T + b4)
    sgemm_bias_relu<<<dim3((IN_DIM + BN - 1) / BN, BATCH / BM), blk>>>(d, W4, b4, out, BATCH, IN_DIM, INTER);
}

// round 3
// speedup vs baseline: 13.4704x; 13.4704x over previous
#include <cuda_runtime.h>
#include <cuda_bf16.h>

// Problem constants
#define BATCH   16384
#define IN_DIM  784
#define INTER   1024
#define CODE    2048   // STRIPE_DIM(64) * NUM_STRIPES(32)
#define KNEUR   64
#define KSTRIPE 4
#define NSTRIPE 32

// Scratch (device globals; no allocation allowed)
__device__ float g_h[(size_t)BATCH * INTER];     // 64 MB
__device__ float g_c[(size_t)BATCH * CODE];      // 128 MB
__device__ float g_d[(size_t)BATCH * INTER];     // 64 MB
__device__ float g_W3t[(size_t)CODE * INTER];    // 8 MB
__device__ float g_vals[(size_t)BATCH * KNEUR];
__device__ int   g_idx[(size_t)BATCH * KNEUR];
__device__ int   g_cnt[BATCH];

// ---------------------------------------------------------------------------
// Compensated fp32 GEMM: C = relu(A[M,K] @ B[N,K]^T + bias[N])
// Accumulates 8 K-steps in a plain fp32 register, then folds into a (hi,lo)
// two-float accumulator via branch-free 2Sum (exact). Residual error is the
// 8-long fp32 chain per chunk: ~sqrt(8)*eps ~ 1.7e-7 relative, enough to
// preserve the reference's top-k decisions downstream.
// Requires M%128==0, N%64==0, K%16==0 (holds for GEMM1/GEMM2).
// BM=128, BN=64, BK=16, 256 threads, 8x4 microtile.
// ---------------------------------------------------------------------------
#define GBM 128
#define GBN 64
#define GBK 16
#define GPAD 4

__global__ __launch_bounds__(256)
void gemm12_comp(const float* __restrict__ A, const float* __restrict__ B,
                 const float* __restrict__ bias, float* __restrict__ C,
                 int M, int N, int K)
{
    __shared__ float As[GBK][GBM + GPAD];
    __shared__ float Bs[GBK][GBN + GPAD];

    const int tid  = threadIdx.x;
    const int row0 = blockIdx.y * GBM;
    const int col0 = blockIdx.x * GBN;
    const int tx = tid % 16;   // 16 col-groups * 4 = 64
    const int ty = tid / 16;   // 16 row-groups * 8 = 128

    float hi[8][4], lo[8][4], ac[8][4];
    #pragma unroll
    for (int i = 0; i < 8; ++i)
        #pragma unroll
        for (int j = 0; j < 4; ++j) { hi[i][j] = 0.f; lo[i][j] = 0.f; ac[i][j] = 0.f; }

    for (int k0 = 0; k0 < K; k0 += GBK) {
        // A tile: 128x16 floats = 512 float4, 2 per thread
        #pragma unroll
        for (int it = 0; it < 2; ++it) {
            int fi = tid + it * 256;
            int r  = fi >> 2;
            int kq = (fi & 3) * 4;
            float4 v = *reinterpret_cast<const float4*>(A + (size_t)(row0 + r) * K + k0 + kq);
            As[kq + 0][r] = v.x; As[kq + 1][r] = v.y;
            As[kq + 2][r] = v.z; As[kq + 3][r] = v.w;
        }
        // B tile: 64x16 floats = 256 float4, 1 per thread
        {
            int r  = tid >> 2;
            int kq = (tid & 3) * 4;
            float4 v = *reinterpret_cast<const float4*>(B + (size_t)(col0 + r) * K + k0 + kq);
            Bs[kq + 0][r] = v.x; Bs[kq + 1][r] = v.y;
            Bs[kq + 2][r] = v.z; Bs[kq + 3][r] = v.w;
        }
        __syncthreads();

        #pragma unroll
        for (int half = 0; half < 2; ++half) {
            #pragma unroll
            for (int k8 = 0; k8 < 8; ++k8) {
                int kk = half * 8 + k8;
                float ra[8], rb[4];
                #pragma unroll
                for (int i = 0; i < 8; ++i) ra[i] = As[kk][ty * 8 + i];
                #pragma unroll
                for (int j = 0; j < 4; ++j) rb[j] = Bs[kk][tx * 4 + j];
                #pragma unroll
                for (int i = 0; i < 8; ++i)
                    #pragma unroll
                    for (int j = 0; j < 4; ++j)
                        ac[i][j] = fmaf(ra[i], rb[j], ac[i][j]);
            }
            // Fold chunk into (hi, lo) via branch-free 2Sum (exact).
            #pragma unroll
            for (int i = 0; i < 8; ++i)
                #pragma unroll
                for (int j = 0; j < 4; ++j) {
                    float a = hi[i][j];
                    float p = ac[i][j];
                    float s  = __fadd_rn(a, p);
                    float ap = __fsub_rn(s, p);
                    float bp = __fsub_rn(s, ap);
                    float da = __fsub_rn(a, ap);
                    float db = __fsub_rn(p, bp);
                    lo[i][j] = __fadd_rn(lo[i][j], __fadd_rn(da, db));
                    hi[i][j] = s;
                    ac[i][j] = 0.f;
                }
        }
        __syncthreads();
    }

    // Epilogue: r = hi + lo + bias, relu, float4 stores (cols contiguous per thread)
    #pragma unroll
    for (int i = 0; i < 8; ++i) {
        int r = row0 + ty * 8 + i;
        float4 bb = *reinterpret_cast<const float4*>(bias + col0 + tx * 4);
        float4 o;
        o.x = fmaxf(__fadd_rn(__fadd_rn(hi[i][0], lo[i][0]), bb.x), 0.f);
        o.y = fmaxf(__fadd_rn(__fadd_rn(hi[i][1], lo[i][1]), bb.y), 0.f);
        o.z = fmaxf(__fadd_rn(__fadd_rn(hi[i][2], lo[i][2]), bb.z), 0.f);
        o.w = fmaxf(__fadd_rn(__fadd_rn(hi[i][3], lo[i][3]), bb.w), 0.f);
        *reinterpret_cast<float4*>(C + (size_t)r * N + col0 + tx * 4) = o;
    }
}

// ---------------------------------------------------------------------------
// Plain fp32 tiled GEMM (GEMM4 — final layer, no selection chaos downstream)
// ---------------------------------------------------------------------------
#define BM 128
#define BN 128
#define BKK 16
#define TM 8
#define TN 8
#define PAD 4

__global__ __launch_bounds__(256)
void sgemm_bias_relu(const float* __restrict__ A, const float* __restrict__ B,
                     const float* __restrict__ bias, float* __restrict__ C,
                     int M, int N, int K)
{
    __shared__ float As[BKK][BM + PAD];
    __shared__ float Bs[BKK][BN + PAD];

    const int tid  = threadIdx.x;
    const int row0 = blockIdx.y * BM;
    const int col0 = blockIdx.x * BN;
    const int tx = tid % 16;
    const int ty = tid / 16;

    float acc[TM][TN];
    #pragma unroll
    for (int i = 0; i < TM; ++i)
        #pragma unroll
        for (int j = 0; j < TN; ++j) acc[i][j] = 0.f;

    for (int k0 = 0; k0 < K; k0 += BKK) {
        #pragma unroll
        for (int it = 0; it < 2; ++it) {
            int fi = tid + it * 256;
            int r  = fi >> 2;
            int kq = (fi & 3) * 4;
            float4 v = *reinterpret_cast<const float4*>(A + (size_t)(row0 + r) * K + k0 + kq);
            As[kq + 0][r] = v.x; As[kq + 1][r] = v.y;
            As[kq + 2][r] = v.z; As[kq + 3][r] = v.w;
        }
        #pragma unroll
        for (int it = 0; it < 2; ++it) {
            int fi = tid + it * 256;
            int r  = fi >> 2;
            int kq = (fi & 3) * 4;
            float4 v = make_float4(0.f, 0.f, 0.f, 0.f);
            if (col0 + r < N)
                v = *reinterpret_cast<const float4*>(B + (size_t)(col0 + r) * K + k0 + kq);
            Bs[kq + 0][r] = v.x; Bs[kq + 1][r] = v.y;
            Bs[kq + 2][r] = v.z; Bs[kq + 3][r] = v.w;
        }
        __syncthreads();

        #pragma unroll
        for (int kk = 0; kk < BKK; ++kk) {
            float ra[TM], rb[TN];
            #pragma unroll
            for (int i = 0; i < TM; ++i) ra[i] = As[kk][ty * TM + i];
            #pragma unroll
            for (int j = 0; j < TN; ++j) rb[j] = Bs[kk][tx * TN + j];
            #pragma unroll
            for (int i = 0; i < TM; ++i)
                #pragma unroll
                for (int j = 0; j < TN; ++j)
                    acc[i][j] = fmaf(ra[i], rb[j], acc[i][j]);
        }
        __syncthreads();
    }

    #pragma unroll
    for (int i = 0; i < TM; ++i) {
        int r = row0 + ty * TM + i;
        #pragma unroll
        for (int j = 0; j < TN; ++j) {
            int c = col0 + tx * TN + j;
            if (c < N)
                C[(size_t)r * N + c] = fmaxf(acc[i][j] + bias[c], 0.f);
        }
    }
}

// ---------------------------------------------------------------------------
// W3 [1024,2048] -> g_W3t [2048,1024]
// ---------------------------------------------------------------------------
__global__ void transpose_w3(const float* __restrict__ W3)
{
    __shared__ float t[32][33];
    int x = blockIdx.x * 32 + threadIdx.x;
    int y = blockIdx.y * 32 + threadIdx.y;
    t[threadIdx.y][threadIdx.x] = W3[(size_t)y * CODE + x];
    __syncthreads();
    int xo = blockIdx.y * 32 + threadIdx.x;
    int yo = blockIdx.x * 32 + threadIdx.y;
    g_W3t[(size_t)yo * INTER + xo] = t[threadIdx.x][threadIdx.y];
}

// ---------------------------------------------------------------------------
// Per-row top-64 of 2048 (radix select on fp32 bits; all values >= 0),
// stripe sums in fp64, top-4-of-32 stripes, compact (idx, val) emission.
// ---------------------------------------------------------------------------
__global__ __launch_bounds__(256)
void topk_compact()
{
    const int row = blockIdx.x;
    const int tid = threadIdx.x;

    __shared__ unsigned bits[CODE];
    __shared__ unsigned hist[256];
    __shared__ unsigned s_prefix;
    __shared__ int s_k;
    __shared__ double s_sum[NSTRIPE];
    __shared__ int s_mask[NSTRIPE];
    __shared__ int s_cnt;

    const unsigned* crow = reinterpret_cast<const unsigned*>(g_c + (size_t)row * CODE);
    #pragma unroll
    for (int i = 0; i < 2; ++i) {
        int f = tid + i * 256;
        reinterpret_cast<uint4*>(bits)[f] = reinterpret_cast<const uint4*>(crow)[f];
    }
    if (tid == 0) { s_prefix = 0u; s_k = KNEUR; s_cnt = 0; }
    __syncthreads();

    for (int p = 3; p >= 0; --p) {
        hist[tid] = 0u;
        __syncthreads();
        unsigned prefix = s_prefix;
        unsigned himask = (p == 3) ? 0u : (0xFFFFFFFFu << ((p + 1) * 8));
        #pragma unroll
        for (int i = 0; i < 8; ++i) {
            unsigned b = bits[tid * 8 + i];
            if ((b & himask) == prefix)
                atomicAdd(&hist[(b >> (p * 8)) & 0xFFu], 1u);
        }
        __syncthreads();
        if (tid == 0) {
            int k = s_k;
            unsigned acc = 0;
            int sel = 0;
            for (int bin = 255; bin >= 0; --bin) {
                unsigned h = hist[bin];
                if (acc + h >= (unsigned)k) { sel = bin; break; }
                acc += h;
            }
            s_prefix = prefix | ((unsigned)sel << (p * 8));
            s_k = k - (int)acc;
        }
        __syncthreads();
    }
    const unsigned T = s_prefix;

    float mv[8];
    double partial = 0.0;
    #pragma unroll
    for (int i = 0; i < 8; ++i) {
        unsigned b = bits[tid * 8 + i];
        float v = __uint_as_float(b);
        float m = (b >= T) ? v : 0.f;
        mv[i] = m;
        partial += (double)m;
    }
    partial += __shfl_down_sync(0xffffffffu, partial, 4);
    partial += __shfl_down_sync(0xffffffffu, partial, 2);
    partial += __shfl_down_sync(0xffffffffu, partial, 1);
    if ((tid & 7) == 0) s_sum[tid >> 3] = partial;
    __syncthreads();

    if (tid < NSTRIPE) {
        double my = s_sum[tid];
        int c = 0;
        #pragma unroll
        for (int j = 0; j < NSTRIPE; ++j) c += (s_sum[j] > my);
        s_mask[tid] = (c < KSTRIPE);
    }
    __syncthreads();

    const int keep = s_mask[tid >> 3];
    #pragma unroll
    for (int i = 0; i < 8; ++i) {
        float m = mv[i];
        if (keep && m > 0.f) {
            int pos = atomicAdd(&s_cnt, 1);
            if (pos < KNEUR) {
                g_vals[(size_t)row * KNEUR + pos] = m;
                g_idx[(size_t)row * KNEUR + pos]  = tid * 8 + i;
            }
        }
    }
    __syncthreads();
    if (tid == 0) g_cnt[row] = min(s_cnt, KNEUR);
}

// ---------------------------------------------------------------------------
// Sparse decode: d[row,:] = relu(b3 + sum_i val_i * W3t[idx_i, :])
// ---------------------------------------------------------------------------
__global__ __launch_bounds__(256)
void sparse_decode(const float* __restrict__ b3)
{
    const int row = blockIdx.x;
    const int tid = threadIdx.x;
    __shared__ float sv[KNEUR];
    __shared__ int   si[KNEUR];

    const int cnt = g_cnt[row];
    if (tid < cnt) {
        sv[tid] = g_vals[(size_t)row * KNEUR + tid];
        si[tid] = g_idx[(size_t)row * KNEUR + tid];
    }
    __syncthreads();

    float4 acc = make_float4(0.f, 0.f, 0.f, 0.f);
    for (int i = 0; i < cnt; ++i) {
        float v = sv[i];
        float4 w = *reinterpret_cast<const float4*>(&g_W3t[(size_t)si[i] * INTER + tid * 4]);
        acc.x = fmaf(v, w.x, acc.x);
        acc.y = fmaf(v, w.y, acc.y);
        acc.z = fmaf(v, w.z, acc.z);
        acc.w = fmaf(v, w.w, acc.w);
    }
    float4 bb = *reinterpret_cast<const float4*>(b3 + tid * 4);
    float4 o;
    o.x = fmaxf(acc.x + bb.x, 0.f);
    o.y = fmaxf(acc.y + bb.y, 0.f);
    o.z = fmaxf(acc.z + bb.z, 0.f);
    o.w = fmaxf(acc.w + bb.w, 0.f);
    *reinterpret_cast<float4*>(&g_d[(size_t)row * INTER + tid * 4]) = o;
}

// ---------------------------------------------------------------------------
// Launch
// ---------------------------------------------------------------------------
extern "C" void kernel_launch(void* const* d_in, const int* in_sizes, int n_in,
                              void* d_out, int out_size)
{
    const float* x  = (const float*)d_in[0];
    const float* W1 = (const float*)d_in[1];
    const float* b1 = (const float*)d_in[2];
    const float* W2 = (const float*)d_in[3];
    const float* b2 = (const float*)d_in[4];
    const float* W3 = (const float*)d_in[5];
    const float* b3 = (const float*)d_in[6];
    const float* W4 = (const float*)d_in[7];
    const float* b4 = (const float*)d_in[8];
    float* out = (float*)d_out;

    float* h = nullptr; cudaGetSymbolAddress((void**)&h, g_h);
    float* c = nullptr; cudaGetSymbolAddress((void**)&c, g_c);
    float* d = nullptr; cudaGetSymbolAddress((void**)&d, g_d);

    dim3 blk(256);

    transpose_w3<<<dim3(CODE / 32, INTER / 32), dim3(32, 32)>>>(W3);

    // GEMM1 (compensated fp32): h = relu(x @ W1^T + b1)
    gemm12_comp<<<dim3(INTER / GBN, BATCH / GBM), blk>>>(x, W1, b1, h, BATCH, INTER, IN_DIM);

    // GEMM2 (compensated fp32): c = relu(h @ W2^T + b2)
    gemm12_comp<<<dim3(CODE / GBN, BATCH / GBM), blk>>>(h, W2, b2, c, BATCH, CODE, INTER);

    // Top-k masks + compaction
    topk_compact<<<BATCH, blk>>>();

    // Sparse GEMM3: d = relu(c_sparse @ W3^T + b3)
    sparse_decode<<<BATCH, blk>>>(b3);

    // GEMM4 (fp32): out = relu(d @ W4^T + b4)
    sgemm_bias_relu<<<dim3((IN_DIM + BN - 1) / BN, BATCH / BM), blk>>>(d, W4, b4, out, BATCH, IN_DIM, INTER);
}